// round 17
// baseline (speedup 1.0000x reference)
#include <cuda_runtime.h>
#include <math.h>

#define BB 2
#define HH 1024
#define WW 1024
#define NPIX (HH*WW)
#define KK 16
#define NBINS 2048                 // merged fine grid over e in [0,2), w = 1/1024
#define FINE0 1536                 // neg fine region: e >= 1.5
#define NFINE (NBINS-FINE0)        // 512
#define NCOARSE 12                 // neg coarse bins over [0,1.5), w = 0.125 (= 128 fine bins)
#define CHUNKS 37
#define CHUNK_PIX ((NPIX + CHUNKS - 1)/CHUNKS)

// ---------------- scratch (static device globals) ----------------
__device__ double g_acc[BB*KK*12];   // 0 cnt,1 sx,2 sy,3 ccnt,4 csx,5 csy,6 s0,7 s1,8 s0sq,9 s1sq,10 seedsq
__device__ double g_seedbg[BB];
__device__ double g_sd2[BB*KK];      // sum dist^2 over pos
__device__ double g_ssd[BB*KK];      // sum seed*dist over pos
__device__ float  g_lov[BB*KK];
__device__ float  g_params[BB*KK*8]; // 0 cx,1 cy,2 sxv,3 syv,4 present,5 varnum,6 seedsq,7 count
__device__ unsigned int g_pos[BB*KK*NBINS];
__device__ unsigned int g_negf[BB*KK*NFINE];
__device__ unsigned int g_cc[BB*KK*NCOARSE];
__device__ float        g_cs[BB*KK*NCOARSE];
__device__ unsigned int g_cen_nonzero;
__device__ float2 g_exy[BB*NPIX];
__device__ float  g_seed[BB*NPIX];

// ---------------- kernel 0: zero accumulators ----------------
__global__ void zero_kernel() {
    int idx = blockIdx.x * blockDim.x + threadIdx.x;
    int stride = gridDim.x * blockDim.x;
    for (int i = idx; i < BB*KK*NBINS; i += stride) g_pos[i] = 0u;
    for (int i = idx; i < BB*KK*NFINE; i += stride) g_negf[i] = 0u;
    if (idx < BB*KK*NCOARSE) { g_cc[idx] = 0u; g_cs[idx] = 0.f; }
    if (idx < BB*KK*12) g_acc[idx] = 0.0;
    if (idx < BB*KK) { g_sd2[idx] = 0.0; g_ssd[idx] = 0.0; g_lov[idx] = 0.f; }
    if (idx < BB) g_seedbg[idx] = 0.0;
    if (idx == 0) g_cen_nonzero = 0u;
}

// ---------------- kernel 1: detect center_images dtype (bool u8 vs int32) ----
__global__ void detect_kernel(const unsigned char* __restrict__ cen) {
    unsigned int local = 0;
    int stride = gridDim.x * blockDim.x;
    for (int i = blockIdx.x*blockDim.x + threadIdx.x; i < BB*NPIX; i += stride) {
        if ((i & 3) && cen[i]) local++;
    }
    #pragma unroll
    for (int o = 16; o; o >>= 1) local += __shfl_down_sync(0xffffffffu, local, o);
    if ((threadIdx.x & 31) == 0 && local) atomicAdd(&g_cen_nonzero, local);
}

// ---------------- kernel 2: per-pixel pass 1 ----------------
__global__ void __launch_bounds__(256) pass1_kernel(
    const float* __restrict__ pred, const int* __restrict__ inst,
    const int* __restrict__ lab, const unsigned char* __restrict__ cen)
{
    __shared__ float sacc[KK*12];
    __shared__ float sbg;
    int b = blockIdx.y;
    for (int t = threadIdx.x; t < KK*12; t += 256) sacc[t] = 0.f;
    if (threadIdx.x == 0) sbg = 0.f;
    __syncthreads();

    bool cen_i32 = (g_cen_nonzero == 0u);
    const int* cen_i = (const int*)cen;
    const float* pb = pred + (size_t)b * 5 * NPIX;
    size_t boff = (size_t)b * NPIX;
    float bg_local = 0.f;
    int start = blockIdx.x * 4096;

    #pragma unroll 4
    for (int r = 0; r < 16; r++) {
        int i = start + r*256 + threadIdx.x;
        float xm = (float)(i & 1023) * (1.f/1023.f);
        float ym = (float)(i >> 10)  * (1.f/1023.f);
        float a0 = pb[i];
        float a1 = pb[NPIX + i];
        float a4 = pb[4*NPIX + i];
        float ex = tanhf(a0) + xm;
        float ey = tanhf(a1) + ym;
        float sd = 1.f / (1.f + __expf(-a4));
        g_exy[boff + i] = make_float2(ex, ey);
        g_seed[boff + i] = sd;

        int iv = inst[boff + i];
        if (iv >= 1 && iv <= KK) {
            float a2 = pb[2*NPIX + i];
            float a3 = pb[3*NPIX + i];
            float* s = &sacc[(iv-1)*12];
            atomicAdd(s+0, 1.f);
            atomicAdd(s+1, xm);
            atomicAdd(s+2, ym);
            atomicAdd(s+6, a2);
            atomicAdd(s+7, a3);
            atomicAdd(s+8, a2*a2);
            atomicAdd(s+9, a3*a3);
            atomicAdd(s+10, sd*sd);
            bool c = cen_i32 ? (cen_i[boff + i] != 0) : (cen[boff + i] != 0);
            if (c) {
                atomicAdd(s+3, 1.f);
                atomicAdd(s+4, xm);
                atomicAdd(s+5, ym);
            }
        }
        if (lab[boff + i] == 0) bg_local += sd * sd;
    }
    #pragma unroll
    for (int o = 16; o; o >>= 1) bg_local += __shfl_down_sync(0xffffffffu, bg_local, o);
    if ((threadIdx.x & 31) == 0) atomicAdd(&sbg, bg_local);
    __syncthreads();

    for (int t = threadIdx.x; t < KK*12; t += 256) {
        float v = sacc[t];
        if (v != 0.f) atomicAdd(&g_acc[b*KK*12 + t], (double)v);
    }
    if (threadIdx.x == 0) atomicAdd(&g_seedbg[b], (double)sbg);
}

// ---------------- kernel 3: per-instance params ----------------
__global__ void param_kernel() {
    int t = blockIdx.x * blockDim.x + threadIdx.x;
    if (t >= BB*KK) return;
    const double* a = &g_acc[t*12];
    double count = a[0];
    float present = count > 0.0 ? 1.f : 0.f;
    double cnt = count > 0.0 ? count : 1.0;
    double cx, cy;
    if (a[3] == 1.0) { cx = a[4]; cy = a[5]; }
    else             { cx = a[1] / cnt; cy = a[2] / cnt; }
    double sm0 = a[6] / cnt;
    double sm1 = a[7] / cnt;
    // var numerator: sum(sig - smean)^2 over both channels
    double varnum = (a[8] - a[6]*a[6]/cnt) + (a[9] - a[7]*a[7]/cnt);
    float* p = &g_params[t*8];
    p[0] = (float)cx; p[1] = (float)cy;
    p[2] = expf(10.f * (float)sm0); p[3] = expf(10.f * (float)sm1);
    p[4] = present; p[5] = (float)varnum; p[6] = (float)a[10]; p[7] = (float)count;
}

// ---------------- kernel 4: dist + hybrid fine/coarse binning ----------------
__global__ void __launch_bounds__(512) hist_kernel(const int* __restrict__ inst)
{
    int b = blockIdx.z, k = blockIdx.y, chunk = blockIdx.x;
    int bk = b*KK + k;
    const float* p = &g_params[bk*8];
    if (p[4] == 0.f) return;   // absent instance: all terms weighted by present=0

    __shared__ unsigned int spos[NBINS];     // pos counts, full range, 8KB
    __shared__ unsigned int sneg[NFINE];     // neg counts, e >= 1.5, 2KB
    for (int t = threadIdx.x; t < NBINS; t += 512) spos[t] = 0u;
    for (int t = threadIdx.x; t < NFINE; t += 512) sneg[t] = 0u;
    __syncthreads();

    float cx = p[0], cy = p[1], sxv = p[2], syv = p[3];
    size_t boff = (size_t)b * NPIX;
    int target = k + 1;
    int start = chunk * CHUNK_PIX;
    int end = start + CHUNK_PIX; if (end > NPIX) end = NPIX;

    unsigned int ccnt[NCOARSE];
    float csum[NCOARSE];
    #pragma unroll
    for (int j = 0; j < NCOARSE; j++) { ccnt[j] = 0u; csum[j] = 0.f; }
    float sd2 = 0.f, ssd = 0.f;

    for (int i = start + threadIdx.x; i < end; i += 512) {
        float2 xy = g_exy[boff + i];
        int iv = inst[boff + i];
        float dx = xy.x - cx, dy = xy.y - cy;
        float q = dx*dx*sxv + dy*dy*syv;
        float d = __expf(-q);
        bool pos = (iv == target);
        float e = pos ? fmaf(-2.f, d, 2.f) : 2.f*d;
        int ib = (int)(e * 1024.f);
        ib = min(ib, NBINS - 1);
        if (pos) {
            atomicAdd(&spos[ib], 1u);
            sd2 += d*d;
            ssd += g_seed[boff + i] * d;
        } else if (ib >= FINE0) {
            atomicAdd(&sneg[ib - FINE0], 1u);
        } else {
            int cb = ib >> 7;   // 128 fine bins per coarse bin
            #pragma unroll
            for (int j = 0; j < NCOARSE; j++) {
                bool m = (cb == j);
                ccnt[j] += m ? 1u : 0u;
                csum[j] += m ? e : 0.f;
            }
        }
    }

    // warp-reduce register accumulators, then global red
    int lane = threadIdx.x & 31;
    #pragma unroll
    for (int o = 16; o; o >>= 1) {
        sd2 += __shfl_down_sync(0xffffffffu, sd2, o);
        ssd += __shfl_down_sync(0xffffffffu, ssd, o);
    }
    if (lane == 0) {
        atomicAdd(&g_sd2[bk], (double)sd2);
        atomicAdd(&g_ssd[bk], (double)ssd);
    }
    #pragma unroll
    for (int j = 0; j < NCOARSE; j++) {
        unsigned int c = ccnt[j];
        float s = csum[j];
        #pragma unroll
        for (int o = 16; o; o >>= 1) {
            c += __shfl_down_sync(0xffffffffu, c, o);
            s += __shfl_down_sync(0xffffffffu, s, o);
        }
        if (lane == 0 && c) {
            atomicAdd(&g_cc[bk*NCOARSE + j], c);
            atomicAdd(&g_cs[bk*NCOARSE + j], s);
        }
    }
    __syncthreads();
    unsigned int* gp = &g_pos[(size_t)bk * NBINS];
    for (int t = threadIdx.x; t < NBINS; t += 512) {
        unsigned int v = spos[t];
        if (v) atomicAdd(&gp[t], v);
    }
    unsigned int* gn = &g_negf[(size_t)bk * NFINE];
    for (int t = threadIdx.x; t < NFINE; t += 512) {
        unsigned int v = sneg[t];
        if (v) atomicAdd(&gn[t], v);
    }
}

// ---------------- kernel 5: Lovasz via descending histogram scan -------------
__global__ void __launch_bounds__(1024) lovasz_kernel() {
    int k = blockIdx.x, b = blockIdx.y;
    int bk = b*KK + k;
    const float* p = &g_params[bk*8];
    if (p[4] == 0.f) { if (threadIdx.x == 0) g_lov[bk] = 0.f; return; }
    float gtsf = p[7];

    __shared__ unsigned int snc[NBINS];
    for (int idx = threadIdx.x; idx < NBINS; idx += 1024)
        snc[idx] = (idx >= FINE0) ? g_negf[(size_t)bk*NFINE + idx - FINE0] : 0u;
    __syncthreads();
    // inject mean-matched coarse masses into the fine grid
    if (threadIdx.x < NCOARSE) {
        unsigned int c = g_cc[bk*NCOARSE + threadIdx.x];
        if (c) {
            float mean = g_cs[bk*NCOARSE + threadIdx.x] / (float)c;
            int m = (int)(mean * 1024.f);
            m = min(max(m, 0), FINE0 - 1);
            atomicAdd(&snc[m], c);
        }
    }
    __syncthreads();

    const unsigned int* hpos = &g_pos[(size_t)bk * NBINS];
    int t = threadIdx.x;
    int lane = t & 31, warp = t >> 5;

    const int PER_T = NBINS / 1024;   // 2
    unsigned int np[PER_T], nn[PER_T];
    unsigned int csum = 0, psum = 0;
    #pragma unroll
    for (int r = 0; r < PER_T; r++) {
        int bin = NBINS - 1 - (t*PER_T + r);   // descending error order
        np[r] = hpos[bin]; nn[r] = snc[bin];
        csum += np[r] + nn[r]; psum += np[r];
    }
    unsigned long long v = ((unsigned long long)psum << 32) | (unsigned long long)csum;
    unsigned long long inc = v;
    #pragma unroll
    for (int o = 1; o < 32; o <<= 1) {
        unsigned long long u = __shfl_up_sync(0xffffffffu, inc, o);
        if (lane >= o) inc += u;
    }
    __shared__ unsigned long long wsum[32];
    if (lane == 31) wsum[warp] = inc;
    __syncthreads();
    if (warp == 0) {
        unsigned long long w = wsum[lane];
        #pragma unroll
        for (int o = 1; o < 32; o <<= 1) {
            unsigned long long u = __shfl_up_sync(0xffffffffu, w, o);
            if (lane >= o) w += u;
        }
        wsum[lane] = w;
    }
    __syncthreads();
    unsigned long long ex = inc - v + (warp > 0 ? wsum[warp-1] : 0ULL);

    double i  = (double)(unsigned int)(ex & 0xffffffffULL);
    double P  = (double)(unsigned int)(ex >> 32);
    double gts = (double)gtsf;
    double jb = 1.0 - (gts - P) / (gts + i - P);
    double contrib = 0.0;
    #pragma unroll
    for (int r = 0; r < PER_T; r++) {
        unsigned int c = np[r] + nn[r];
        if (c) {
            int bin = NBINS - 1 - (t*PER_T + r);
            i += (double)c; P += (double)np[r];
            double ja = 1.0 - (gts - P) / (gts + i - P);
            double e = ((double)bin + 0.5) * (2.0 / NBINS);
            contrib += e * (ja - jb);
            jb = ja;
        }
    }
    #pragma unroll
    for (int o = 16; o; o >>= 1) contrib += __shfl_down_sync(0xffffffffu, contrib, o);
    __shared__ double cred[32];
    if (lane == 0) cred[warp] = contrib;
    __syncthreads();
    if (t == 0) {
        double s = 0.0;
        for (int w = 0; w < 32; w++) s += cred[w];
        g_lov[bk] = (float)s;
    }
}

// ---------------- kernel 6: final combine ----------------
__global__ void final_kernel(float* out) {
    double total = 0.0;
    for (int b = 0; b < BB; b++) {
        double sum_pres = 0.0, inst_s = 0.0, var_s = 0.0, sfg_s = 0.0;
        for (int k = 0; k < KK; k++) {
            int bk = b*KK + k;
            const float* p = &g_params[bk*8];
            double pres = (double)p[4];
            double cnt = p[7] > 0.f ? (double)p[7] : 1.0;
            sum_pres += pres;
            inst_s += (double)g_lov[bk] * pres;
            var_s  += ((double)p[5] / (2.0 * cnt)) * pres;                 // N_SIGMA = 2
            double sfg = (double)p[6] - 2.0*g_ssd[bk] + g_sd2[bk];         // sum(seed-dist)^2
            sfg_s  += sfg * pres;                                          // FG_W = 1
        }
        double obj = sum_pres > 1.0 ? sum_pres : 1.0;
        double seed_loss = (g_seedbg[b] + sfg_s) / (double)(HH * WW);
        total += (inst_s / obj) + 10.0 * (var_s / obj) + seed_loss;        // W_INST=1,W_VAR=10,W_SEED=1
    }
    *out = (float)(total / BB);
}

// ---------------- launch ----------------
extern "C" void kernel_launch(void* const* d_in, const int* in_sizes, int n_in,
                              void* d_out, int out_size)
{
    const float* pred = (const float*)d_in[0];
    const int*   inst = (const int*)d_in[2];
    const int*   lab  = (const int*)d_in[3];
    const unsigned char* cen = (const unsigned char*)d_in[4];
    float* out = (float*)d_out;

    zero_kernel<<<256, 256>>>();
    detect_kernel<<<128, 256>>>(cen);
    pass1_kernel<<<dim3(NPIX/4096, BB), 256>>>(pred, inst, lab, cen);
    param_kernel<<<1, 32>>>();
    hist_kernel<<<dim3(CHUNKS, KK, BB), 512>>>(inst);
    lovasz_kernel<<<dim3(KK, BB), 1024>>>();
    final_kernel<<<1, 1>>>(out);
}